// round 6
// baseline (speedup 1.0000x reference)
#include <cuda_runtime.h>
#include <cuda_fp16.h>
#include <cstdint>

// Problem constants
#define MDIM 8192
#define NDIM 11008
#define KDIM 4096

#define BM 128
#define BN 128
#define BK 64
#define PAD 8
#define LDS_W (BK + PAD)        // 72 halfs per smem row
#define NTHREADS 256
#define KTILES (KDIM / BK)      // 64

static_assert(MDIM % BM == 0 && NDIM % BN == 0 && KDIM % BK == 0, "tiling");

__device__ __forceinline__ void mma16816(float acc[4],
    uint32_t a0, uint32_t a1, uint32_t a2, uint32_t a3,
    uint32_t b0, uint32_t b1)
{
    asm volatile(
        "mma.sync.aligned.m16n8k16.row.col.f32.f16.f16.f32 "
        "{%0,%1,%2,%3},{%4,%5,%6,%7},{%8,%9},{%0,%1,%2,%3};"
        : "+f"(acc[0]), "+f"(acc[1]), "+f"(acc[2]), "+f"(acc[3])
        : "r"(a0), "r"(a1), "r"(a2), "r"(a3), "r"(b0), "r"(b1));
}

__device__ __forceinline__ uint32_t h2_u32(__half2 h) {
    return *reinterpret_cast<uint32_t*>(&h);
}

__global__ void __launch_bounds__(NTHREADS, 2)
w4a16_gemm_kernel(const float* __restrict__ x,        // fp32 carrying fp16 values
                  const int* __restrict__ wp,
                  const float* __restrict__ scales,   // fp32 carrying fp16 values
                  float* __restrict__ out)            // fp32 output
{
    __shared__ __half As[BM][LDS_W];
    __shared__ __half Bs[BN][LDS_W];

    const int tid = threadIdx.x;
    const int bm = blockIdx.x;      // M fastest -> B panel reused from L2
    const int bn = blockIdx.y;
    const int m0 = bm * BM;
    const int n0 = bn * BN;

    const int lrow = tid >> 3;      // 0..31
    const int lvec = tid & 7;       // 0..7

    const float* xBase = x + (size_t)m0 * KDIM;
    const int*   wBase = wp + (size_t)n0 * (KDIM / 2);
    const float* sBase = scales + (size_t)n0 * 32;

    uint4 aReg[4];      // 8 halfs per thread-row, already converted
    int4  bReg[4];
    float sReg[4];

    auto load_tile = [&](int kt) {
        const int k0 = kt * BK;
        #pragma unroll
        for (int i = 0; i < 4; i++) {
            const int row = i * 32 + lrow;
            const float* ap = xBase + (size_t)row * KDIM + k0 + lvec * 8;
            float4 f0 = *reinterpret_cast<const float4*>(ap);
            float4 f1 = *reinterpret_cast<const float4*>(ap + 4);
            aReg[i].x = h2_u32(__floats2half2_rn(f0.x, f0.y));   // lossless: values are fp16
            aReg[i].y = h2_u32(__floats2half2_rn(f0.z, f0.w));
            aReg[i].z = h2_u32(__floats2half2_rn(f1.x, f1.y));
            aReg[i].w = h2_u32(__floats2half2_rn(f1.z, f1.w));
            bReg[i] = *reinterpret_cast<const int4*>(
                wBase + (size_t)row * (KDIM / 2) + (k0 >> 1) + lvec * 4);
            sReg[i] = sBase[row * 32 + (k0 >> 7)];   // group = k0/128
        }
    };

    const __half2 c1032 = __half2half2(__ushort_as_half(0x6408)); // 1032.0 exact

    auto store_tile = [&]() {
        #pragma unroll
        for (int i = 0; i < 4; i++) {
            const int row = i * 32 + lrow;
            *reinterpret_cast<uint4*>(&As[row][lvec * 8]) = aReg[i];

            const __half2 s2 = __half2half2(__float2half_rn(sReg[i]));
            uint32_t v[4] = { (uint32_t)bReg[i].x, (uint32_t)bReg[i].y,
                              (uint32_t)bReg[i].z, (uint32_t)bReg[i].w };
            uint32_t h[4];
            #pragma unroll
            for (int j = 0; j < 4; j++) {
                // int32 element holds one byte: low nibble -> even k, high nibble -> odd k
                uint32_t t = (v[j] & 0xFu) | ((v[j] << 12) & 0x000F0000u) | 0x64006400u;
                __half2 hh = *reinterpret_cast<__half2*>(&t);
                hh = __hmul2(__hsub2(hh, c1032), s2);   // (w-8) exact, one rounding on *s
                h[j] = *reinterpret_cast<uint32_t*>(&hh);
            }
            uint4 pack = make_uint4(h[0], h[1], h[2], h[3]);
            *reinterpret_cast<uint4*>(&Bs[row][lvec * 8]) = pack;
        }
    };

    // ---- warp layout: 2 (M) x 4 (N) warps; warp tile 64x32 ----
    const int warp = tid >> 5;
    const int lane = tid & 31;
    const int wm = warp & 1;
    const int wn = warp >> 1;
    const int gid = lane >> 2;      // groupID  (0..7)
    const int tig = lane & 3;       // thread in group (0..3)

    float acc[4][4][4];
    #pragma unroll
    for (int i = 0; i < 4; i++)
        #pragma unroll
        for (int j = 0; j < 4; j++)
            #pragma unroll
            for (int c = 0; c < 4; c++) acc[i][j][c] = 0.f;

    // Fragment loads straight from PTX m16n8k16 tables.
    auto compute_tile = [&]() {
        #pragma unroll
        for (int ks = 0; ks < 4; ks++) {
            const int kb = ks * 16 + tig * 2;
            uint32_t bf[4][2];
            #pragma unroll
            for (int nt = 0; nt < 4; nt++) {
                const __half* Bp = &Bs[wn * 32 + nt * 8 + gid][kb];
                bf[nt][0] = *reinterpret_cast<const uint32_t*>(Bp);      // k, k+1
                bf[nt][1] = *reinterpret_cast<const uint32_t*>(Bp + 8);  // k+8, k+9
            }
            #pragma unroll
            for (int mt = 0; mt < 4; mt++) {
                const __half* Ap = &As[wm * 64 + mt * 16 + gid][kb];
                uint32_t a0 = *reinterpret_cast<const uint32_t*>(Ap);                 // r,   c
                uint32_t a1 = *reinterpret_cast<const uint32_t*>(Ap + 8 * LDS_W);     // r+8, c
                uint32_t a2 = *reinterpret_cast<const uint32_t*>(Ap + 8);             // r,   c+8
                uint32_t a3 = *reinterpret_cast<const uint32_t*>(Ap + 8 * LDS_W + 8); // r+8, c+8
                #pragma unroll
                for (int nt = 0; nt < 4; nt++)
                    mma16816(acc[mt][nt], a0, a1, a2, a3, bf[nt][0], bf[nt][1]);
            }
        }
    };

    // ---- main loop: single smem buffer, register prefetch hides gmem latency ----
    load_tile(0);
    for (int t = 0; t < KTILES; t++) {
        __syncthreads();            // previous compute done before overwrite
        store_tile();               // regs hold tile t
        __syncthreads();            // tile visible
        if (t + 1 < KTILES) load_tile(t + 1);
        compute_tile();
    }

    // ---- epilogue: fp32 acc -> fp16 rounding (match reference) -> fp32 store ----
    float* outBase = out + (size_t)(m0 + wm * 64) * NDIM + n0 + wn * 32;
    const int r = gid;
    const int c = tig * 2;
    #pragma unroll
    for (int mt = 0; mt < 4; mt++) {
        #pragma unroll
        for (int nt = 0; nt < 4; nt++) {
            float v0 = __half2float(__float2half_rn(acc[mt][nt][0]));
            float v1 = __half2float(__float2half_rn(acc[mt][nt][1]));
            float v2 = __half2float(__float2half_rn(acc[mt][nt][2]));
            float v3 = __half2float(__float2half_rn(acc[mt][nt][3]));
            *reinterpret_cast<float2*>(outBase + (size_t)(mt * 16 + r) * NDIM + nt * 8 + c)
                = make_float2(v0, v1);
            *reinterpret_cast<float2*>(outBase + (size_t)(mt * 16 + 8 + r) * NDIM + nt * 8 + c)
                = make_float2(v2, v3);
        }
    }
}

extern "C" void kernel_launch(void* const* d_in, const int* in_sizes, int n_in,
                              void* d_out, int out_size) {
    // Dispatch inputs by element count (dtype-independent, robust to ordering).
    //   x            : 8192*4096  = 33,554,432  (float32 carrying fp16 values)
    //   weight_packed: 11008*2048 = 22,544,384  (int32)
    //   scales       : 11008*32   =    352,256  (float32 carrying fp16 values)
    const float* x      = nullptr;
    const int*   wp     = nullptr;
    const float* scales = nullptr;
    for (int i = 0; i < n_in; i++) {
        if      (in_sizes[i] == 33554432) x      = (const float*)d_in[i];
        else if (in_sizes[i] == 22544384) wp     = (const int*)d_in[i];
        else if (in_sizes[i] == 352256)   scales = (const float*)d_in[i];
    }
    float* out = (float*)d_out;
    if (!x || !wp || !scales) return;

    dim3 grid(MDIM / BM, NDIM / BN);    // (64, 86)
    dim3 block(NTHREADS);
    w4a16_gemm_kernel<<<grid, block>>>(x, wp, scales, out);
}